// round 9
// baseline (speedup 1.0000x reference)
#include <cuda_runtime.h>
#include <math.h>

// features: (B=16, C=256, H=64, W=64) fp32 ; out: (B, H, W) fp32
//
// R9 = R5 mapping (channel quarter per warp-group: q=tid>>6, 32 adjacent
// pixels per warp -> every warp-LDG is one 128B line; grid=1024, block=256)
// with the inner loop manually staged in batches of 8 scalar loads into
// explicit temporaries BEFORE any accumulation: forces ptxas to emit 8
// back-to-back LDG.E.32 with immediate offsets (max MLP_p1), covering the
// L1tex queue + L2 latency instead of interleaving load/FMA.

#define C_DIM   256
#define HW      4096
#define NPIX    65536
#define TPB     256
#define PIX_PER_BLK 64

__global__ void __launch_bounds__(TPB)
fis_kernel(const float* __restrict__ f,
           const float* __restrict__ W1,   // (3,16)
           const float* __restrict__ b1,   // 16
           const float* __restrict__ W2,   // (16,1)
           const float* __restrict__ b2,   // 1
           float* __restrict__ out)
{
    __shared__ float sp[81];          // [0:48) W1, [48:64) b1, [64:80) W2, [80] b2
    __shared__ float red_s [4][PIX_PER_BLK];
    __shared__ float red_ss[4][PIX_PER_BLK];

    int tid = threadIdx.x;
    if (tid < 81) {
        float v;
        if (tid < 48)      v = W1[tid];
        else if (tid < 64) v = b1[tid - 48];
        else if (tid < 80) v = W2[tid - 64];
        else               v = b2[0];
        sp[tid] = v;
    }
    __syncthreads();

    int q = tid >> 6;                 // channel quarter [0,4)
    int i = tid & 63;                 // pixel within block
    int p = blockIdx.x * PIX_PER_BLK + i;

    int b  = p >> 12;
    int hw = p & (HW - 1);
    const float* __restrict__ src =
        f + (size_t)b * C_DIM * HW + (size_t)(q * 64) * HW + hw;

    float s = 0.f, ss = 0.f;

    // 64 channels in 8 batches of 8: loads issued before any consumption.
    #pragma unroll
    for (int c0 = 0; c0 < 64; c0 += 8) {
        float v0 = __ldg(src + (size_t)(c0 + 0) * HW);
        float v1 = __ldg(src + (size_t)(c0 + 1) * HW);
        float v2 = __ldg(src + (size_t)(c0 + 2) * HW);
        float v3 = __ldg(src + (size_t)(c0 + 3) * HW);
        float v4 = __ldg(src + (size_t)(c0 + 4) * HW);
        float v5 = __ldg(src + (size_t)(c0 + 5) * HW);
        float v6 = __ldg(src + (size_t)(c0 + 6) * HW);
        float v7 = __ldg(src + (size_t)(c0 + 7) * HW);

        s += v0; ss = fmaf(v0, v0, ss);
        s += v1; ss = fmaf(v1, v1, ss);
        s += v2; ss = fmaf(v2, v2, ss);
        s += v3; ss = fmaf(v3, v3, ss);
        s += v4; ss = fmaf(v4, v4, ss);
        s += v5; ss = fmaf(v5, v5, ss);
        s += v6; ss = fmaf(v6, v6, ss);
        s += v7; ss = fmaf(v7, v7, ss);
    }

    red_s [q][i] = s;
    red_ss[q][i] = ss;
    __syncthreads();

    if (tid < PIX_PER_BLK) {
        float sv  = red_s [0][tid] + red_s [1][tid] + red_s [2][tid] + red_s [3][tid];
        float ssv = red_ss[0][tid] + red_ss[1][tid] + red_ss[2][tid] + red_ss[3][tid];

        const float inv_c  = 1.0f / 256.0f;
        const float inv_c1 = 1.0f / 255.0f;
        float mag = sqrtf(ssv * inv_c);
        float var = (ssv - sv * sv * inv_c) * inv_c1;
        var = fmaxf(var, 0.0f);
        float sd  = sqrtf(var);

        float x0 = fminf(mag, 1.0f);
        float x1 = fminf(var, 1.0f);
        float x2 = fminf(sd,  1.0f);

        float acc = sp[80];
        #pragma unroll
        for (int o = 0; o < 16; ++o) {
            float h = sp[48 + o];
            h = fmaf(x0, sp[o],      h);
            h = fmaf(x1, sp[16 + o], h);
            h = fmaf(x2, sp[32 + o], h);
            h = fmaxf(h, 0.0f);
            acc = fmaf(h, sp[64 + o], acc);
        }
        out[blockIdx.x * PIX_PER_BLK + tid] = 1.0f / (1.0f + __expf(-acc));
    }
}

extern "C" void kernel_launch(void* const* d_in, const int* in_sizes, int n_in,
                              void* d_out, int out_size)
{
    const float* f  = (const float*)d_in[0];
    const float* W1 = (const float*)d_in[1];
    const float* b1 = (const float*)d_in[2];
    const float* W2 = (const float*)d_in[3];
    const float* b2 = (const float*)d_in[4];
    float* out = (float*)d_out;

    fis_kernel<<<NPIX / PIX_PER_BLK, TPB>>>(f, W1, b1, W2, b2, out);
}

// round 10
// speedup vs baseline: 1.6358x; 1.6358x over previous
#include <cuda_runtime.h>
#include <math.h>

// features: (B=16, C=256, H=64, W=64) fp32 ; out: (B, H, W) fp32
//
// R10 = R5 mapping (channel quarter per 64-thread group; each warp = one
// quarter x 32 adjacent pixels -> every warp-LDG is exactly one 128B line;
// interleaved load/accumulate to keep MLP_p1 low per the R9 spread lesson)
// + __launch_bounds__(256,7): 36-reg target so all 1024 blocks are resident
// in ONE wave (7x148=1036), removing R5's 136-block ragged tail without
// hitting R6's 8-block contention point. unroll 16 for scheduling window.

#define C_DIM   256
#define HW      4096
#define NPIX    65536
#define TPB     256
#define PIX_PER_BLK 64

__global__ void __launch_bounds__(TPB, 7)
fis_kernel(const float* __restrict__ f,
           const float* __restrict__ W1,   // (3,16)
           const float* __restrict__ b1,   // 16
           const float* __restrict__ W2,   // (16,1)
           const float* __restrict__ b2,   // 1
           float* __restrict__ out)
{
    __shared__ float sp[81];          // [0:48) W1, [48:64) b1, [64:80) W2, [80] b2
    __shared__ float red_s [4][PIX_PER_BLK];
    __shared__ float red_ss[4][PIX_PER_BLK];

    int tid = threadIdx.x;
    if (tid < 81) {
        float v;
        if (tid < 48)      v = W1[tid];
        else if (tid < 64) v = b1[tid - 48];
        else if (tid < 80) v = W2[tid - 64];
        else               v = b2[0];
        sp[tid] = v;
    }
    __syncthreads();

    int q = tid >> 6;                 // channel quarter [0,4)
    int i = tid & 63;                 // pixel within block
    int p = blockIdx.x * PIX_PER_BLK + i;

    int b  = p >> 12;
    int hw = p & (HW - 1);
    const float* __restrict__ src =
        f + (size_t)b * C_DIM * HW + (size_t)(q * 64) * HW + hw;

    float s = 0.f, ss = 0.f;
    #pragma unroll 16
    for (int c = 0; c < 64; ++c) {
        float v = __ldg(src + (size_t)c * HW);
        s += v;
        ss = fmaf(v, v, ss);
    }

    red_s [q][i] = s;
    red_ss[q][i] = ss;
    __syncthreads();

    if (tid < PIX_PER_BLK) {
        float sv  = red_s [0][tid] + red_s [1][tid] + red_s [2][tid] + red_s [3][tid];
        float ssv = red_ss[0][tid] + red_ss[1][tid] + red_ss[2][tid] + red_ss[3][tid];

        const float inv_c  = 1.0f / 256.0f;
        const float inv_c1 = 1.0f / 255.0f;
        float mag = sqrtf(ssv * inv_c);
        float var = (ssv - sv * sv * inv_c) * inv_c1;
        var = fmaxf(var, 0.0f);
        float sd  = sqrtf(var);

        float x0 = fminf(mag, 1.0f);
        float x1 = fminf(var, 1.0f);
        float x2 = fminf(sd,  1.0f);

        float acc = sp[80];
        #pragma unroll
        for (int o = 0; o < 16; ++o) {
            float h = sp[48 + o];
            h = fmaf(x0, sp[o],      h);
            h = fmaf(x1, sp[16 + o], h);
            h = fmaf(x2, sp[32 + o], h);
            h = fmaxf(h, 0.0f);
            acc = fmaf(h, sp[64 + o], acc);
        }
        out[blockIdx.x * PIX_PER_BLK + tid] = 1.0f / (1.0f + __expf(-acc));
    }
}

extern "C" void kernel_launch(void* const* d_in, const int* in_sizes, int n_in,
                              void* d_out, int out_size)
{
    const float* f  = (const float*)d_in[0];
    const float* W1 = (const float*)d_in[1];
    const float* b1 = (const float*)d_in[2];
    const float* W2 = (const float*)d_in[3];
    const float* b2 = (const float*)d_in[4];
    float* out = (float*)d_out;

    fis_kernel<<<NPIX / PIX_PER_BLK, TPB>>>(f, W1, b1, W2, b2, out);
}